// round 10
// baseline (speedup 1.0000x reference)
#include <cuda_runtime.h>
#include <cuda_fp16.h>
#include <cstdint>

// Problem constants (fixed by the dataset)
#define BB   16
#define NN   4096
#define SS   1024
#define KK   32
#define DIN  64
#define DINC 67
#define DOUT 64

#define ROWS_P 64         // rows per proj CTA (2+ waves -> stage/MMA/store pipeline)

// k16 step ranges inside the shared operand buffers:
//   ks 0..3 : phase A (x @ W2, K=64)
//   ks 4..8 : phase B (xc @ W1, K=67 padded to 80)

// Scratch (static device globals: allocation-free per harness rules)
__device__ float g_sum[(size_t)BB * NN * DOUT];   // xc@W1 + bias (+ xp if use_x)
__device__ float g_xp [(size_t)BB * NN * DOUT];   // xp = x@W2 (center subtraction)

// ---------------------------------------------------------------------------
// SMEM layout (bytes)
//   A buf: [ks][row:64][4 x uint2]  atom(row,j) = {f16x2 pair j, pair j+4}
//   B buf: [ks][n:64][4 x uint2]    same structure
// swizzle: stored slot = (j&3) ^ (row&3)  -> conflict-free LDS.64
// ---------------------------------------------------------------------------
#define SAB   0                         // 9*64*32 = 18432
#define SBB   18432                     // 9*64*32 = 18432
#define SBIAS 36864                     // 256
#define SMEM_BYTES 37120

// fp16x2 pack: lo half = v0, hi half = v1
__device__ __forceinline__ uint32_t pack_h2(float v0, float v1) {
    __half2 h = __floats2half2_rn(v0, v1);
    return *(uint32_t*)&h;
}

// m16n8k16 fp16 MMA with fp32 accumulate, D += A*B (D aliases C)
__device__ __forceinline__ void mma16(float* d, uint32_t a0, uint32_t a1, uint32_t a2,
                                      uint32_t a3, uint32_t b0, uint32_t b1) {
    asm volatile(
        "mma.sync.aligned.m16n8k16.row.col.f32.f16.f16.f32 "
        "{%0,%1,%2,%3}, {%4,%5,%6,%7}, {%8,%9}, {%0,%1,%2,%3};"
        : "+f"(d[0]), "+f"(d[1]), "+f"(d[2]), "+f"(d[3])
        : "r"(a0), "r"(a1), "r"(a2), "r"(a3), "r"(b0), "r"(b1));
}

// GEMM phase over ks in [ks0, ks1): warp computes 32 rows x 16 cols
// (2 m-tiles x 2 n-tiles = 4 MMAs per k-step, independent accumulators).
__device__ __forceinline__ void gemm_phase(
    const uint2* abuf, const uint2* bbuf, int ks0, int ks1,
    float acc[2][2][4], const int rA[2], const int nI[2], int km)
{
    for (int ks = ks0; ks < ks1; ks++) {
        uint2 A0[2], A1[2], Bv[2];
        #pragma unroll
        for (int tM = 0; tM < 2; tM++) {
            int r0 = rA[tM], r1 = rA[tM] + 8;
            A0[tM] = abuf[(ks * 64 + r0) * 4 + (km ^ (r0 & 3))];
            A1[tM] = abuf[(ks * 64 + r1) * 4 + (km ^ (r1 & 3))];
        }
        #pragma unroll
        for (int tN = 0; tN < 2; tN++) {
            int n = nI[tN];
            Bv[tN] = bbuf[(ks * 64 + n) * 4 + (km ^ (n & 3))];
        }
        #pragma unroll
        for (int tM = 0; tM < 2; tM++)
            #pragma unroll
            for (int tN = 0; tN < 2; tN++)
                mma16(acc[tM][tN], A0[tM].x, A1[tM].x, A0[tM].y, A1[tM].y, Bv[tN].x, Bv[tN].y);
    }
}

// ---------------------------------------------------------------------------
// proj_mma: per CTA computes 64 rows of g_xp and g_sum via fp16 MMA.
// ---------------------------------------------------------------------------
__global__ void __launch_bounds__(256) proj_mma(
    const float* __restrict__ x, const float* __restrict__ xcm,
    const float* __restrict__ w1, const float* __restrict__ w2,
    const float* __restrict__ bias, const int* __restrict__ use_x)
{
    extern __shared__ char smem[];
    uint32_t* sA = (uint32_t*)(smem + SAB);
    uint32_t* sB = (uint32_t*)(smem + SBB);
    float*    sBias = (float*)(smem + SBIAS);

    const int tid  = threadIdx.x;
    const int wid  = tid >> 5;
    const int lane = tid & 31;
    const int ux   = use_x[0];
    const size_t base = (size_t)blockIdx.x * ROWS_P;

    // ---- stage W2 [64 n][64 k] -> B ks 0..3 ----
    for (int i = tid; i < 64 * 32; i += 256) {
        int n = i >> 5, jj32 = i & 31;
        int ks = jj32 >> 3, jj = jj32 & 7;
        int k0 = ks * 16 + 2 * jj;
        uint32_t p = pack_h2(w2[n * DIN + k0], w2[n * DIN + k0 + 1]);
        int a2 = (ks * 64 + n) * 4 + ((jj & 3) ^ (n & 3));
        sB[a2 * 2 + (jj >> 2)] = p;
    }
    // ---- stage W1 [64 n][67 k -> 80] -> B ks 4..8 ----
    for (int i = tid; i < 64 * 40; i += 256) {
        int n = i / 40, jj40 = i - n * 40;
        int ksl = jj40 >> 3, jj = jj40 & 7;
        int k0 = ksl * 16 + 2 * jj;
        float v0 = (k0     < DINC) ? w1[n * DINC + k0]     : 0.0f;
        float v1 = (k0 + 1 < DINC) ? w1[n * DINC + k0 + 1] : 0.0f;
        uint32_t p = pack_h2(v0, v1);
        int ks = 4 + ksl;
        int a2 = (ks * 64 + n) * 4 + ((jj & 3) ^ (n & 3));
        sB[a2 * 2 + (jj >> 2)] = p;
    }
    if (tid < DOUT) sBias[tid] = bias[tid];
    // ---- stage x tile [64][64] -> A ks 0..3 ----
    if (ux) {
        const float* src = x + base * DIN;
        for (int i = tid; i < 64 * 32; i += 256) {
            int r = i >> 5, jj32 = i & 31;
            int ks = jj32 >> 3, jj = jj32 & 7;
            int k0 = ks * 16 + 2 * jj;
            uint32_t p = pack_h2(src[r * DIN + k0], src[r * DIN + k0 + 1]);
            int a2 = (ks * 64 + r) * 4 + ((jj & 3) ^ (r & 3));
            sA[a2 * 2 + (jj >> 2)] = p;
        }
    }
    // ---- stage xc tile [64][67 -> 80] -> A ks 4..8 ----
    {
        const float* src = xcm + base * DINC;
        for (int i = tid; i < 64 * 40; i += 256) {
            int r = i / 40, jj40 = i - r * 40;
            int ksl = jj40 >> 3, jj = jj40 & 7;
            int k0 = ksl * 16 + 2 * jj;
            float v0 = (k0     < DINC) ? src[r * DINC + k0]     : 0.0f;
            float v1 = (k0 + 1 < DINC) ? src[r * DINC + k0 + 1] : 0.0f;
            uint32_t p = pack_h2(v0, v1);
            int ks = 4 + ksl;
            int a2 = (ks * 64 + r) * 4 + ((jj & 3) ^ (r & 3));
            sA[a2 * 2 + (jj >> 2)] = p;
        }
    }
    __syncthreads();

    // ---- per-warp fragment coordinates (warp grid 2M x 4N; 32x16 per warp) --
    const int warpM = wid >> 2;            // 0..1
    const int warpN = wid & 3;             // 0..3
    const int km    = lane & 3;            // k-pair selector
    const int qr    = lane >> 2;           // 0..7
    int rA[2], nI[2];
    #pragma unroll
    for (int tM = 0; tM < 2; tM++) rA[tM] = warpM * 32 + tM * 16 + qr;
    #pragma unroll
    for (int tN = 0; tN < 2; tN++) nI[tN] = warpN * 16 + tN * 8 + qr;

    float acc[2][2][4];
    #pragma unroll
    for (int i = 0; i < 2; i++)
        #pragma unroll
        for (int j = 0; j < 2; j++)
            #pragma unroll
            for (int q = 0; q < 4; q++) acc[i][j][q] = 0.0f;

    const int colq = 2 * (lane & 3);

    // ---- Phase A: acc = x @ W2^T ; write g_xp ----
    if (ux) {
        gemm_phase((const uint2*)sA, (const uint2*)sB, 0, 4, acc, rA, nI, km);
        #pragma unroll
        for (int tM = 0; tM < 2; tM++) {
            int r = rA[tM];
            #pragma unroll
            for (int tN = 0; tN < 2; tN++) {
                int cc = warpN * 16 + tN * 8 + colq;
                float* p = g_xp + (base + r) * DOUT + cc;
                *(float2*)p = make_float2(acc[tM][tN][0], acc[tM][tN][1]);
                *(float2*)(p + 8 * DOUT) = make_float2(acc[tM][tN][2], acc[tM][tN][3]);
            }
        }
    }

    // ---- Phase B: acc += xc @ W1^T ; write g_sum = acc + bias ----
    gemm_phase((const uint2*)sA, (const uint2*)sB, 4, 9, acc, rA, nI, km);

    #pragma unroll
    for (int tM = 0; tM < 2; tM++) {
        int r = rA[tM];
        #pragma unroll
        for (int tN = 0; tN < 2; tN++) {
            int cc = warpN * 16 + tN * 8 + colq;
            float2 bv = *(const float2*)(sBias + cc);
            float* p = g_sum + (base + r) * DOUT + cc;
            *(float2*)p = make_float2(acc[tM][tN][0] + bv.x, acc[tM][tN][1] + bv.y);
            *(float2*)(p + 8 * DOUT) = make_float2(acc[tM][tN][2] + bv.x, acc[tM][tN][3] + bv.y);
        }
    }
}

// ---------------------------------------------------------------------------
// Pool kernel (proven R3 version: single 1024-block launch, ~14.3us).
// ---------------------------------------------------------------------------
__global__ void __launch_bounds__(256) pool_kernel(
    const void* __restrict__ indexes, const int* __restrict__ use_x,
    float* __restrict__ out)
{
    __shared__ int sidx[512];           // 16 pairs x 32 idx
    const int tid = threadIdx.x;
    const size_t blk = blockIdx.x;      // 1024 blocks

    // dtype detection: reads in-bounds under BOTH interpretations
    int2 v = ((const int2*)indexes)[blk * 256 + tid];
    bool pok = (v.y == (v.x < 0 ? -1 : 0));
    int is64 = __syncthreads_and(pok);

    if (is64) {
        longlong2 q = ((const longlong2*)indexes)[blk * 256 + tid];
        sidx[2 * tid]     = (int)q.x;
        sidx[2 * tid + 1] = (int)q.y;
    } else {
        sidx[2 * tid]     = v.x;
        sidx[2 * tid + 1] = v.y;
    }
    __syncthreads();

    const int grp    = tid >> 4;
    const int lane16 = tid & 15;
    const size_t p   = blk * 16 + grp;
    const int b      = (int)(p >> 10);
    const int* myidx = sidx + grp * 32;

    const float* sumb = g_sum + (size_t)b * NN * DOUT;
    const int c0 = lane16 * 4;
    const int id0 = myidx[0];

    const int ux = use_x[0];
    float4 cen = make_float4(0.f, 0.f, 0.f, 0.f);
    if (ux)
        cen = *(const float4*)(g_xp + ((size_t)b * NN + id0) * DOUT + c0);

    float4 a[8];
    #pragma unroll
    for (int q = 0; q < 8; q++) a[q] = make_float4(-3.4e38f, -3.4e38f, -3.4e38f, -3.4e38f);

    #pragma unroll
    for (int q = 0; q < 8; q++) {
        int4 iq = ((const int4*)myidx)[q];
        int j0 = iq.x < 0 ? id0 : iq.x;
        int j1 = iq.y < 0 ? id0 : iq.y;
        int j2 = iq.z < 0 ? id0 : iq.z;
        int j3 = iq.w < 0 ? id0 : iq.w;
        float4 v0 = *(const float4*)(sumb + (size_t)j0 * DOUT + c0);
        float4 v1 = *(const float4*)(sumb + (size_t)j1 * DOUT + c0);
        float4 v2 = *(const float4*)(sumb + (size_t)j2 * DOUT + c0);
        float4 v3 = *(const float4*)(sumb + (size_t)j3 * DOUT + c0);
        float4 m01, m23;
        m01.x = fmaxf(v0.x, v1.x); m01.y = fmaxf(v0.y, v1.y); m01.z = fmaxf(v0.z, v1.z); m01.w = fmaxf(v0.w, v1.w);
        m23.x = fmaxf(v2.x, v3.x); m23.y = fmaxf(v2.y, v3.y); m23.z = fmaxf(v2.z, v3.z); m23.w = fmaxf(v2.w, v3.w);
        a[q].x = fmaxf(m01.x, m23.x); a[q].y = fmaxf(m01.y, m23.y);
        a[q].z = fmaxf(m01.z, m23.z); a[q].w = fmaxf(m01.w, m23.w);
    }

    #pragma unroll
    for (int st = 4; st > 0; st >>= 1)
        #pragma unroll
        for (int q = 0; q < st; q++) {
            a[q].x = fmaxf(a[q].x, a[q + st].x);
            a[q].y = fmaxf(a[q].y, a[q + st].y);
            a[q].z = fmaxf(a[q].z, a[q + st].z);
            a[q].w = fmaxf(a[q].w, a[q + st].w);
        }

    float4 o = make_float4(a[0].x - cen.x, a[0].y - cen.y, a[0].z - cen.z, a[0].w - cen.w);
    *(float4*)(out + p * DOUT + c0) = o;
}

// ---------------------------------------------------------------------------
// Launcher (single stream, 2 launches)
// ---------------------------------------------------------------------------
extern "C" void kernel_launch(void* const* d_in, const int* in_sizes, int n_in,
                              void* d_out, int out_size)
{
    const float* x    = (const float*)d_in[0];
    const float* xcm  = (const float*)d_in[1];
    const void*  idx  = d_in[2];
    const float* w1   = (const float*)d_in[3];
    const float* w2   = (const float*)d_in[4];
    const float* bias = (const float*)d_in[5];
    const int*   ux   = (const int*)d_in[6];

    cudaFuncSetAttribute(proj_mma, cudaFuncAttributeMaxDynamicSharedMemorySize, SMEM_BYTES);

    proj_mma<<<(BB * NN) / ROWS_P, 256, SMEM_BYTES>>>(x, xcm, w1, w2, bias, ux);
    pool_kernel<<<(BB * SS) / 16, 256>>>(idx, ux, (float*)d_out);
}

// round 11
// speedup vs baseline: 1.1165x; 1.1165x over previous
#include <cuda_runtime.h>
#include <cuda_fp16.h>
#include <cstdint>

// Problem constants (fixed by the dataset)
#define BB   16
#define NN   4096
#define SS   1024
#define KK   32
#define DIN  64
#define DINC 67
#define DOUT 64

// k16 step ranges inside the shared operand buffers:
//   ks 0..3 : phase A (x @ W2, K=64)
//   ks 4..8 : phase B (xc @ W1, K=67 padded to 80)

// Scratch (static device globals: allocation-free per harness rules)
__device__ float g_sum[(size_t)BB * NN * DOUT];   // xc@W1 + bias (+ xp if use_x)
__device__ float g_xp [(size_t)BB * NN * DOUT];   // xp = x@W2 (center subtraction)

// ---------------------------------------------------------------------------
// SMEM layout (bytes)  [R9 config: 128 rows/CTA]
//   A buf: [ks][row:128][4 x uint2]  atom(row,j) = {f16x2 pair j, pair j+4}
//   B buf: [ks][n:64][4 x uint2]     same structure
// swizzle: stored slot = (j&3) ^ (row&3)  -> conflict-free LDS.64
// ---------------------------------------------------------------------------
#define SAB   0                         // 9*128*32 = 36864
#define SBB   36864                     // 9*64*32  = 18432
#define SBIAS 55296                     // 256
#define SMEM_BYTES 55552

// fp16x2 pack: lo half = v0, hi half = v1
__device__ __forceinline__ uint32_t pack_h2(float v0, float v1) {
    __half2 h = __floats2half2_rn(v0, v1);
    return *(uint32_t*)&h;
}

// m16n8k16 fp16 MMA with fp32 accumulate, D += A*B (D aliases C)
__device__ __forceinline__ void mma16(float* d, uint32_t a0, uint32_t a1, uint32_t a2,
                                      uint32_t a3, uint32_t b0, uint32_t b1) {
    asm volatile(
        "mma.sync.aligned.m16n8k16.row.col.f32.f16.f16.f32 "
        "{%0,%1,%2,%3}, {%4,%5,%6,%7}, {%8,%9}, {%0,%1,%2,%3};"
        : "+f"(d[0]), "+f"(d[1]), "+f"(d[2]), "+f"(d[3])
        : "r"(a0), "r"(a1), "r"(a2), "r"(a3), "r"(b0), "r"(b1));
}

// GEMM phase over ks in [ks0, ks1): warp computes 32 rows x 32 cols
// (2 m-tiles x 4 n-tiles = 8 MMAs per k-step, independent accumulators).
__device__ __forceinline__ void gemm_phase(
    const uint2* abuf, const uint2* bbuf, int ks0, int ks1,
    float acc[2][4][4], const int rA[2], const int nI[4], int km)
{
    for (int ks = ks0; ks < ks1; ks++) {
        uint2 A0[2], A1[2], Bv[4];
        #pragma unroll
        for (int tM = 0; tM < 2; tM++) {
            int r0 = rA[tM], r1 = rA[tM] + 8;
            A0[tM] = abuf[(ks * 128 + r0) * 4 + (km ^ (r0 & 3))];
            A1[tM] = abuf[(ks * 128 + r1) * 4 + (km ^ (r1 & 3))];
        }
        #pragma unroll
        for (int tN = 0; tN < 4; tN++) {
            int n = nI[tN];
            Bv[tN] = bbuf[(ks * 64 + n) * 4 + (km ^ (n & 3))];
        }
        #pragma unroll
        for (int tM = 0; tM < 2; tM++)
            #pragma unroll
            for (int tN = 0; tN < 4; tN++)
                mma16(acc[tM][tN], A0[tM].x, A1[tM].x, A0[tM].y, A1[tM].y, Bv[tN].x, Bv[tN].y);
    }
}

// ---------------------------------------------------------------------------
// proj_mma: per CTA computes 128 rows of g_xp and g_sum via fp16 MMA. (R9)
// ---------------------------------------------------------------------------
__global__ void __launch_bounds__(256) proj_mma(
    const float* __restrict__ x, const float* __restrict__ xcm,
    const float* __restrict__ w1, const float* __restrict__ w2,
    const float* __restrict__ bias, const int* __restrict__ use_x)
{
    extern __shared__ char smem[];
    uint32_t* sA = (uint32_t*)(smem + SAB);
    uint32_t* sB = (uint32_t*)(smem + SBB);
    float*    sBias = (float*)(smem + SBIAS);

    const int tid  = threadIdx.x;
    const int wid  = tid >> 5;
    const int lane = tid & 31;
    const int ux   = use_x[0];
    const size_t base = (size_t)blockIdx.x * 128;

    // ---- stage W2 [64 n][64 k] -> B ks 0..3 ----
    for (int i = tid; i < 64 * 32; i += 256) {
        int n = i >> 5, jj32 = i & 31;
        int ks = jj32 >> 3, jj = jj32 & 7;
        int k0 = ks * 16 + 2 * jj;
        uint32_t p = pack_h2(w2[n * DIN + k0], w2[n * DIN + k0 + 1]);
        int a2 = (ks * 64 + n) * 4 + ((jj & 3) ^ (n & 3));
        sB[a2 * 2 + (jj >> 2)] = p;
    }
    // ---- stage W1 [64 n][67 k -> 80] -> B ks 4..8 ----
    for (int i = tid; i < 64 * 40; i += 256) {
        int n = i / 40, jj40 = i - n * 40;
        int ksl = jj40 >> 3, jj = jj40 & 7;
        int k0 = ksl * 16 + 2 * jj;
        float v0 = (k0     < DINC) ? w1[n * DINC + k0]     : 0.0f;
        float v1 = (k0 + 1 < DINC) ? w1[n * DINC + k0 + 1] : 0.0f;
        uint32_t p = pack_h2(v0, v1);
        int ks = 4 + ksl;
        int a2 = (ks * 64 + n) * 4 + ((jj & 3) ^ (n & 3));
        sB[a2 * 2 + (jj >> 2)] = p;
    }
    if (tid < DOUT) sBias[tid] = bias[tid];
    // ---- stage x tile [128][64] -> A ks 0..3 ----
    if (ux) {
        const float* src = x + base * DIN;
        for (int i = tid; i < 128 * 32; i += 256) {
            int r = i >> 5, jj32 = i & 31;
            int ks = jj32 >> 3, jj = jj32 & 7;
            int k0 = ks * 16 + 2 * jj;
            uint32_t p = pack_h2(src[r * DIN + k0], src[r * DIN + k0 + 1]);
            int a2 = (ks * 128 + r) * 4 + ((jj & 3) ^ (r & 3));
            sA[a2 * 2 + (jj >> 2)] = p;
        }
    }
    // ---- stage xc tile [128][67 -> 80] -> A ks 4..8 ----
    {
        const float* src = xcm + base * DINC;
        for (int i = tid; i < 128 * 40; i += 256) {
            int r = i / 40, jj40 = i - r * 40;
            int ksl = jj40 >> 3, jj = jj40 & 7;
            int k0 = ksl * 16 + 2 * jj;
            float v0 = (k0     < DINC) ? src[r * DINC + k0]     : 0.0f;
            float v1 = (k0 + 1 < DINC) ? src[r * DINC + k0 + 1] : 0.0f;
            uint32_t p = pack_h2(v0, v1);
            int ks = 4 + ksl;
            int a2 = (ks * 128 + r) * 4 + ((jj & 3) ^ (r & 3));
            sA[a2 * 2 + (jj >> 2)] = p;
        }
    }
    __syncthreads();

    // ---- per-warp fragment coordinates (warp grid 4M x 2N; 32x32 per warp) --
    const int warpM = wid >> 1;            // 0..3
    const int warpN = wid & 1;             // 0..1
    const int km    = lane & 3;            // k-pair selector
    const int qr    = lane >> 2;           // 0..7
    int rA[2], nI[4];
    #pragma unroll
    for (int tM = 0; tM < 2; tM++) rA[tM] = warpM * 32 + tM * 16 + qr;
    #pragma unroll
    for (int tN = 0; tN < 4; tN++) nI[tN] = warpN * 32 + tN * 8 + qr;

    float acc[2][4][4];
    #pragma unroll
    for (int i = 0; i < 2; i++)
        #pragma unroll
        for (int j = 0; j < 4; j++)
            #pragma unroll
            for (int q = 0; q < 4; q++) acc[i][j][q] = 0.0f;

    const int colq = 2 * (lane & 3);

    // ---- Phase A: acc = x @ W2^T ; write g_xp ----
    if (ux) {
        gemm_phase((const uint2*)sA, (const uint2*)sB, 0, 4, acc, rA, nI, km);
        #pragma unroll
        for (int tM = 0; tM < 2; tM++) {
            int r = rA[tM];
            #pragma unroll
            for (int tN = 0; tN < 4; tN++) {
                int cc = warpN * 32 + tN * 8 + colq;
                float* p = g_xp + (base + r) * DOUT + cc;
                *(float2*)p = make_float2(acc[tM][tN][0], acc[tM][tN][1]);
                *(float2*)(p + 8 * DOUT) = make_float2(acc[tM][tN][2], acc[tM][tN][3]);
            }
        }
    }

    // ---- Phase B: acc += xc @ W1^T ; write g_sum = acc + bias ----
    gemm_phase((const uint2*)sA, (const uint2*)sB, 4, 9, acc, rA, nI, km);

    #pragma unroll
    for (int tM = 0; tM < 2; tM++) {
        int r = rA[tM];
        #pragma unroll
        for (int tN = 0; tN < 4; tN++) {
            int cc = warpN * 32 + tN * 8 + colq;
            float2 bv = *(const float2*)(sBias + cc);
            float* p = g_sum + (base + r) * DOUT + cc;
            *(float2*)p = make_float2(acc[tM][tN][0] + bv.x, acc[tM][tN][1] + bv.y);
            *(float2*)(p + 8 * DOUT) = make_float2(acc[tM][tN][2] + bv.x, acc[tM][tN][3] + bv.y);
        }
    }
}

// ---------------------------------------------------------------------------
// Pool kernel (R3 internals) + PDL: prologue (index staging, dtype detect)
// runs while proj drains; griddepcontrol.wait gates the gathers on proj
// completion (block-exit trigger => all proj stores visible).
// ---------------------------------------------------------------------------
__global__ void __launch_bounds__(256) pool_kernel(
    const void* __restrict__ indexes, const int* __restrict__ use_x,
    float* __restrict__ out)
{
    __shared__ int sidx[512];           // 16 pairs x 32 idx
    const int tid = threadIdx.x;
    const size_t blk = blockIdx.x;      // 1024 blocks

    // ---------- prologue: independent of proj output ----------
    int2 v = ((const int2*)indexes)[blk * 256 + tid];
    bool pok = (v.y == (v.x < 0 ? -1 : 0));
    int is64 = __syncthreads_and(pok);

    if (is64) {
        longlong2 q = ((const longlong2*)indexes)[blk * 256 + tid];
        sidx[2 * tid]     = (int)q.x;
        sidx[2 * tid + 1] = (int)q.y;
    } else {
        sidx[2 * tid]     = v.x;
        sidx[2 * tid + 1] = v.y;
    }
    const int ux = use_x[0];
    __syncthreads();

    const int grp    = tid >> 4;
    const int lane16 = tid & 15;
    const size_t p   = blk * 16 + grp;
    const int b      = (int)(p >> 10);
    const int* myidx = sidx + grp * 32;
    const int c0  = lane16 * 4;
    const int id0 = myidx[0];

    // ---------- wait for proj grid completion ----------
    asm volatile("griddepcontrol.wait;" ::: "memory");

    const float* sumb = g_sum + (size_t)b * NN * DOUT;

    float4 cen = make_float4(0.f, 0.f, 0.f, 0.f);
    if (ux)
        cen = *(const float4*)(g_xp + ((size_t)b * NN + id0) * DOUT + c0);

    float4 a[8];
    #pragma unroll
    for (int q = 0; q < 8; q++) a[q] = make_float4(-3.4e38f, -3.4e38f, -3.4e38f, -3.4e38f);

    #pragma unroll
    for (int q = 0; q < 8; q++) {
        int4 iq = ((const int4*)myidx)[q];
        int j0 = iq.x < 0 ? id0 : iq.x;
        int j1 = iq.y < 0 ? id0 : iq.y;
        int j2 = iq.z < 0 ? id0 : iq.z;
        int j3 = iq.w < 0 ? id0 : iq.w;
        float4 v0 = *(const float4*)(sumb + (size_t)j0 * DOUT + c0);
        float4 v1 = *(const float4*)(sumb + (size_t)j1 * DOUT + c0);
        float4 v2 = *(const float4*)(sumb + (size_t)j2 * DOUT + c0);
        float4 v3 = *(const float4*)(sumb + (size_t)j3 * DOUT + c0);
        float4 m01, m23;
        m01.x = fmaxf(v0.x, v1.x); m01.y = fmaxf(v0.y, v1.y); m01.z = fmaxf(v0.z, v1.z); m01.w = fmaxf(v0.w, v1.w);
        m23.x = fmaxf(v2.x, v3.x); m23.y = fmaxf(v2.y, v3.y); m23.z = fmaxf(v2.z, v3.z); m23.w = fmaxf(v2.w, v3.w);
        a[q].x = fmaxf(m01.x, m23.x); a[q].y = fmaxf(m01.y, m23.y);
        a[q].z = fmaxf(m01.z, m23.z); a[q].w = fmaxf(m01.w, m23.w);
    }

    #pragma unroll
    for (int st = 4; st > 0; st >>= 1)
        #pragma unroll
        for (int q = 0; q < st; q++) {
            a[q].x = fmaxf(a[q].x, a[q + st].x);
            a[q].y = fmaxf(a[q].y, a[q + st].y);
            a[q].z = fmaxf(a[q].z, a[q + st].z);
            a[q].w = fmaxf(a[q].w, a[q + st].w);
        }

    float4 o = make_float4(a[0].x - cen.x, a[0].y - cen.y, a[0].z - cen.z, a[0].w - cen.w);
    *(float4*)(out + p * DOUT + c0) = o;
}

// ---------------------------------------------------------------------------
// Launcher: proj (normal) then pool with programmatic stream serialization
// so pool's prologue overlaps proj's tail. Falls back to a plain launch if
// the attributed launch is rejected.
// ---------------------------------------------------------------------------
extern "C" void kernel_launch(void* const* d_in, const int* in_sizes, int n_in,
                              void* d_out, int out_size)
{
    const float* x    = (const float*)d_in[0];
    const float* xcm  = (const float*)d_in[1];
    const void*  idx  = d_in[2];
    const float* w1   = (const float*)d_in[3];
    const float* w2   = (const float*)d_in[4];
    const float* bias = (const float*)d_in[5];
    const int*   ux   = (const int*)d_in[6];
    float* out = (float*)d_out;

    cudaFuncSetAttribute(proj_mma, cudaFuncAttributeMaxDynamicSharedMemorySize, SMEM_BYTES);

    proj_mma<<<(BB * NN) / 128, 256, SMEM_BYTES>>>(x, xcm, w1, w2, bias, ux);

    cudaLaunchConfig_t cfg = {};
    cfg.gridDim  = dim3((BB * SS) / 16, 1, 1);
    cfg.blockDim = dim3(256, 1, 1);
    cfg.dynamicSmemBytes = 0;
    cfg.stream = 0;
    cudaLaunchAttribute attrs[1];
    attrs[0].id = cudaLaunchAttributeProgrammaticStreamSerialization;
    attrs[0].val.programmaticStreamSerializationAllowed = 1;
    cfg.attrs = attrs;
    cfg.numAttrs = 1;

    cudaError_t e = cudaLaunchKernelEx(&cfg, pool_kernel,
                                       (const void*)idx, ux, out);
    if (e != cudaSuccess) {
        // fallback: plain serialized launch (griddepcontrol.wait is a no-op
        // when no programmatic dependence is attached)
        pool_kernel<<<(BB * SS) / 16, 256>>>(idx, ux, out);
    }
}

// round 12
// speedup vs baseline: 1.3344x; 1.1952x over previous
#include <cuda_runtime.h>
#include <cuda_fp16.h>
#include <cstdint>

// Problem constants (fixed by the dataset)
#define BB   16
#define NN   4096
#define SS   1024
#define KK   32
#define DIN  64
#define DINC 67
#define DOUT 64

// Scratch (fp16 intermediates: halves proj-store + pool-gather traffic)
__device__ uint16_t g_sum_h[(size_t)BB * NN * DOUT];   // fp16(xc@W1 + bias (+ xp))
__device__ uint16_t g_xp_h [(size_t)BB * NN * DOUT];   // fp16(x@W2)

// ---------------------------------------------------------------------------
// SMEM layout (bytes)  [proj: 128 rows/CTA, R9 config]
//   A buf: [ks][row:128][4 x uint2]  atom(row,j) = {f16x2 pair j, pair j+4}
//   B buf: [ks][n:64][4 x uint2]     same structure
// swizzle: stored slot = (j&3) ^ (row&3)  -> conflict-free LDS.64
// ---------------------------------------------------------------------------
#define SAB   0                         // 9*128*32 = 36864
#define SBB   36864                     // 9*64*32  = 18432
#define SBIAS 55296                     // 256
#define SMEM_BYTES 55552

// fp16x2 pack: lo half = v0, hi half = v1
__device__ __forceinline__ uint32_t pack_h2(float v0, float v1) {
    __half2 h = __floats2half2_rn(v0, v1);
    return *(uint32_t*)&h;
}

// m16n8k16 fp16 MMA with fp32 accumulate, D += A*B (D aliases C)
__device__ __forceinline__ void mma16(float* d, uint32_t a0, uint32_t a1, uint32_t a2,
                                      uint32_t a3, uint32_t b0, uint32_t b1) {
    asm volatile(
        "mma.sync.aligned.m16n8k16.row.col.f32.f16.f16.f32 "
        "{%0,%1,%2,%3}, {%4,%5,%6,%7}, {%8,%9}, {%0,%1,%2,%3};"
        : "+f"(d[0]), "+f"(d[1]), "+f"(d[2]), "+f"(d[3])
        : "r"(a0), "r"(a1), "r"(a2), "r"(a3), "r"(b0), "r"(b1));
}

// GEMM phase over ks in [ks0, ks1): warp computes 32 rows x 32 cols
__device__ __forceinline__ void gemm_phase(
    const uint2* abuf, const uint2* bbuf, int ks0, int ks1,
    float acc[2][4][4], const int rA[2], const int nI[4], int km)
{
    for (int ks = ks0; ks < ks1; ks++) {
        uint2 A0[2], A1[2], Bv[4];
        #pragma unroll
        for (int tM = 0; tM < 2; tM++) {
            int r0 = rA[tM], r1 = rA[tM] + 8;
            A0[tM] = abuf[(ks * 128 + r0) * 4 + (km ^ (r0 & 3))];
            A1[tM] = abuf[(ks * 128 + r1) * 4 + (km ^ (r1 & 3))];
        }
        #pragma unroll
        for (int tN = 0; tN < 4; tN++) {
            int n = nI[tN];
            Bv[tN] = bbuf[(ks * 64 + n) * 4 + (km ^ (n & 3))];
        }
        #pragma unroll
        for (int tM = 0; tM < 2; tM++)
            #pragma unroll
            for (int tN = 0; tN < 4; tN++)
                mma16(acc[tM][tN], A0[tM].x, A1[tM].x, A0[tM].y, A1[tM].y, Bv[tN].x, Bv[tN].y);
    }
}

// ---------------------------------------------------------------------------
// proj_mma: per CTA computes 128 rows of g_xp_h and g_sum_h via fp16 MMA.
// ---------------------------------------------------------------------------
__global__ void __launch_bounds__(256) proj_mma(
    const float* __restrict__ x, const float* __restrict__ xcm,
    const float* __restrict__ w1, const float* __restrict__ w2,
    const float* __restrict__ bias, const int* __restrict__ use_x)
{
    extern __shared__ char smem[];
    uint32_t* sA = (uint32_t*)(smem + SAB);
    uint32_t* sB = (uint32_t*)(smem + SBB);
    float*    sBias = (float*)(smem + SBIAS);

    const int tid  = threadIdx.x;
    const int wid  = tid >> 5;
    const int lane = tid & 31;
    const int ux   = use_x[0];
    const size_t base = (size_t)blockIdx.x * 128;

    // ---- stage W2 [64 n][64 k] -> B ks 0..3 ----
    for (int i = tid; i < 64 * 32; i += 256) {
        int n = i >> 5, jj32 = i & 31;
        int ks = jj32 >> 3, jj = jj32 & 7;
        int k0 = ks * 16 + 2 * jj;
        uint32_t p = pack_h2(w2[n * DIN + k0], w2[n * DIN + k0 + 1]);
        int a2 = (ks * 64 + n) * 4 + ((jj & 3) ^ (n & 3));
        sB[a2 * 2 + (jj >> 2)] = p;
    }
    // ---- stage W1 [64 n][67 k -> 80] -> B ks 4..8 ----
    for (int i = tid; i < 64 * 40; i += 256) {
        int n = i / 40, jj40 = i - n * 40;
        int ksl = jj40 >> 3, jj = jj40 & 7;
        int k0 = ksl * 16 + 2 * jj;
        float v0 = (k0     < DINC) ? w1[n * DINC + k0]     : 0.0f;
        float v1 = (k0 + 1 < DINC) ? w1[n * DINC + k0 + 1] : 0.0f;
        uint32_t p = pack_h2(v0, v1);
        int ks = 4 + ksl;
        int a2 = (ks * 64 + n) * 4 + ((jj & 3) ^ (n & 3));
        sB[a2 * 2 + (jj >> 2)] = p;
    }
    if (tid < DOUT) sBias[tid] = bias[tid];
    // ---- stage x tile [128][64] -> A ks 0..3 ----
    if (ux) {
        const float* src = x + base * DIN;
        for (int i = tid; i < 128 * 32; i += 256) {
            int r = i >> 5, jj32 = i & 31;
            int ks = jj32 >> 3, jj = jj32 & 7;
            int k0 = ks * 16 + 2 * jj;
            uint32_t p = pack_h2(src[r * DIN + k0], src[r * DIN + k0 + 1]);
            int a2 = (ks * 128 + r) * 4 + ((jj & 3) ^ (r & 3));
            sA[a2 * 2 + (jj >> 2)] = p;
        }
    }
    // ---- stage xc tile [128][67 -> 80] -> A ks 4..8 ----
    {
        const float* src = xcm + base * DINC;
        for (int i = tid; i < 128 * 40; i += 256) {
            int r = i / 40, jj40 = i - r * 40;
            int ksl = jj40 >> 3, jj = jj40 & 7;
            int k0 = ksl * 16 + 2 * jj;
            float v0 = (k0     < DINC) ? src[r * DINC + k0]     : 0.0f;
            float v1 = (k0 + 1 < DINC) ? src[r * DINC + k0 + 1] : 0.0f;
            uint32_t p = pack_h2(v0, v1);
            int ks = 4 + ksl;
            int a2 = (ks * 128 + r) * 4 + ((jj & 3) ^ (r & 3));
            sA[a2 * 2 + (jj >> 2)] = p;
        }
    }
    __syncthreads();

    // ---- per-warp fragment coordinates (warp grid 4M x 2N; 32x32 per warp) --
    const int warpM = wid >> 1;            // 0..3
    const int warpN = wid & 1;             // 0..1
    const int km    = lane & 3;
    const int qr    = lane >> 2;           // 0..7
    int rA[2], nI[4];
    #pragma unroll
    for (int tM = 0; tM < 2; tM++) rA[tM] = warpM * 32 + tM * 16 + qr;
    #pragma unroll
    for (int tN = 0; tN < 4; tN++) nI[tN] = warpN * 32 + tN * 8 + qr;

    float acc[2][4][4];
    #pragma unroll
    for (int i = 0; i < 2; i++)
        #pragma unroll
        for (int j = 0; j < 4; j++)
            #pragma unroll
            for (int q = 0; q < 4; q++) acc[i][j][q] = 0.0f;

    const int colq = 2 * (lane & 3);

    // ---- Phase A: acc = x @ W2^T ; write g_xp_h (fp16) ----
    if (ux) {
        gemm_phase((const uint2*)sA, (const uint2*)sB, 0, 4, acc, rA, nI, km);
        #pragma unroll
        for (int tM = 0; tM < 2; tM++) {
            int r = rA[tM];
            #pragma unroll
            for (int tN = 0; tN < 4; tN++) {
                int cc = warpN * 32 + tN * 8 + colq;
                uint16_t* p = g_xp_h + (base + r) * DOUT + cc;
                *(uint32_t*)p = pack_h2(acc[tM][tN][0], acc[tM][tN][1]);
                *(uint32_t*)(p + 8 * DOUT) = pack_h2(acc[tM][tN][2], acc[tM][tN][3]);
            }
        }
    }

    // ---- Phase B: acc += xc @ W1^T ; write g_sum_h = fp16(acc + bias) ----
    gemm_phase((const uint2*)sA, (const uint2*)sB, 4, 9, acc, rA, nI, km);

    #pragma unroll
    for (int tM = 0; tM < 2; tM++) {
        int r = rA[tM];
        #pragma unroll
        for (int tN = 0; tN < 4; tN++) {
            int cc = warpN * 32 + tN * 8 + colq;
            float2 bv = *(const float2*)(sBias + cc);
            uint16_t* p = g_sum_h + (base + r) * DOUT + cc;
            *(uint32_t*)p = pack_h2(acc[tM][tN][0] + bv.x, acc[tM][tN][1] + bv.y);
            *(uint32_t*)(p + 8 * DOUT) = pack_h2(acc[tM][tN][2] + bv.x, acc[tM][tN][3] + bv.y);
        }
    }
}

// ---------------------------------------------------------------------------
// Pool kernel: 32 pairs/block (8 threads per pair, uint4 = 8 fp16 ch/thread).
// fp16 gathers + __hmax2; PDL gates gathers on proj completion.
// ---------------------------------------------------------------------------
__global__ void __launch_bounds__(256) pool_kernel(
    const void* __restrict__ indexes, const int* __restrict__ use_x,
    float* __restrict__ out)
{
    __shared__ int sidx[1024];          // 32 pairs x 32 idx
    const int tid = threadIdx.x;
    const size_t blk = blockIdx.x;      // 512 blocks

    // ---------- prologue: independent of proj output ----------
    // Detection read: ints [blk*1024, +1024) — this block's idx region if
    // int32; the first half of it if int64. In-bounds either way.
    int4 v = ((const int4*)indexes)[blk * 256 + tid];
    bool pok = (v.y == (v.x < 0 ? -1 : 0)) && (v.w == (v.z < 0 ? -1 : 0));
    int is64 = __syncthreads_and(pok);

    if (is64) {
        longlong2 q0 = ((const longlong2*)indexes)[blk * 512 + 2 * tid];
        longlong2 q1 = ((const longlong2*)indexes)[blk * 512 + 2 * tid + 1];
        sidx[4 * tid]     = (int)q0.x;
        sidx[4 * tid + 1] = (int)q0.y;
        sidx[4 * tid + 2] = (int)q1.x;
        sidx[4 * tid + 3] = (int)q1.y;
    } else {
        sidx[4 * tid]     = v.x;
        sidx[4 * tid + 1] = v.y;
        sidx[4 * tid + 2] = v.z;
        sidx[4 * tid + 3] = v.w;
    }
    const int ux = use_x[0];
    __syncthreads();

    const int grp   = tid >> 3;                 // 0..31: pair within block
    const int lane8 = tid & 7;                  // channel-octet lane
    const size_t p  = blk * 32 + grp;           // global pair id
    const int b     = (int)(p >> 10);
    const int* myidx = sidx + grp * 32;
    const int c0  = lane8 * 8;                  // 8 fp16 channels per thread
    const int id0 = myidx[0];

    // ---------- wait for proj grid completion ----------
    asm volatile("griddepcontrol.wait;" ::: "memory");

    const uint16_t* sumb = g_sum_h + (size_t)b * NN * DOUT;

    float cf[8];
    #pragma unroll
    for (int i = 0; i < 8; i++) cf[i] = 0.0f;
    if (ux) {
        uint4 cr = *(const uint4*)(g_xp_h + ((size_t)b * NN + id0) * DOUT + c0);
        const __half2* ch = (const __half2*)&cr;
        #pragma unroll
        for (int i = 0; i < 4; i++) {
            float2 f = __half22float2(ch[i]);
            cf[2 * i] = f.x; cf[2 * i + 1] = f.y;
        }
    }

    // 4 independent fp16 max accumulators (uint4 = 4 x half2), init -inf
    uint4 a[4];
    #pragma unroll
    for (int q = 0; q < 4; q++)
        a[q] = make_uint4(0xFC00FC00u, 0xFC00FC00u, 0xFC00FC00u, 0xFC00FC00u);

    #pragma unroll
    for (int q = 0; q < 8; q++) {
        int4 iq = ((const int4*)myidx)[q];      // broadcast LDS.128
        int j0 = iq.x < 0 ? id0 : iq.x;
        int j1 = iq.y < 0 ? id0 : iq.y;
        int j2 = iq.z < 0 ? id0 : iq.z;
        int j3 = iq.w < 0 ? id0 : iq.w;
        uint4 v0 = *(const uint4*)(sumb + (size_t)j0 * DOUT + c0);
        uint4 v1 = *(const uint4*)(sumb + (size_t)j1 * DOUT + c0);
        uint4 v2 = *(const uint4*)(sumb + (size_t)j2 * DOUT + c0);
        uint4 v3 = *(const uint4*)(sumb + (size_t)j3 * DOUT + c0);
        __half2* a0 = (__half2*)&a[0]; __half2* a1 = (__half2*)&a[1];
        __half2* a2 = (__half2*)&a[2]; __half2* a3 = (__half2*)&a[3];
        const __half2* h0 = (const __half2*)&v0;
        const __half2* h1 = (const __half2*)&v1;
        const __half2* h2 = (const __half2*)&v2;
        const __half2* h3 = (const __half2*)&v3;
        #pragma unroll
        for (int i = 0; i < 4; i++) {
            a0[i] = __hmax2(a0[i], h0[i]);
            a1[i] = __hmax2(a1[i], h1[i]);
            a2[i] = __hmax2(a2[i], h2[i]);
            a3[i] = __hmax2(a3[i], h3[i]);
        }
    }

    // combine accumulators + center subtraction in fp32
    __half2* a0 = (__half2*)&a[0]; __half2* a1 = (__half2*)&a[1];
    __half2* a2 = (__half2*)&a[2]; __half2* a3 = (__half2*)&a[3];
    float of[8];
    #pragma unroll
    for (int i = 0; i < 4; i++) {
        __half2 m = __hmax2(__hmax2(a0[i], a1[i]), __hmax2(a2[i], a3[i]));
        float2 f = __half22float2(m);
        of[2 * i]     = f.x - cf[2 * i];
        of[2 * i + 1] = f.y - cf[2 * i + 1];
    }

    float* dst = out + p * DOUT + c0;
    *(float4*)dst       = make_float4(of[0], of[1], of[2], of[3]);
    *(float4*)(dst + 4) = make_float4(of[4], of[5], of[6], of[7]);
}

// ---------------------------------------------------------------------------
// Launcher: proj then pool with programmatic stream serialization (PDL).
// ---------------------------------------------------------------------------
extern "C" void kernel_launch(void* const* d_in, const int* in_sizes, int n_in,
                              void* d_out, int out_size)
{
    const float* x    = (const float*)d_in[0];
    const float* xcm  = (const float*)d_in[1];
    const void*  idx  = d_in[2];
    const float* w1   = (const float*)d_in[3];
    const float* w2   = (const float*)d_in[4];
    const float* bias = (const float*)d_in[5];
    const int*   ux   = (const int*)d_in[6];
    float* out = (float*)d_out;

    cudaFuncSetAttribute(proj_mma, cudaFuncAttributeMaxDynamicSharedMemorySize, SMEM_BYTES);

    proj_mma<<<(BB * NN) / 128, 256, SMEM_BYTES>>>(x, xcm, w1, w2, bias, ux);

    cudaLaunchConfig_t cfg = {};
    cfg.gridDim  = dim3((BB * SS) / 32, 1, 1);
    cfg.blockDim = dim3(256, 1, 1);
    cfg.dynamicSmemBytes = 0;
    cfg.stream = 0;
    cudaLaunchAttribute attrs[1];
    attrs[0].id = cudaLaunchAttributeProgrammaticStreamSerialization;
    attrs[0].val.programmaticStreamSerializationAllowed = 1;
    cfg.attrs = attrs;
    cfg.numAttrs = 1;

    cudaError_t e = cudaLaunchKernelEx(&cfg, pool_kernel,
                                       (const void*)idx, ux, out);
    if (e != cudaSuccess) {
        pool_kernel<<<(BB * SS) / 32, 256>>>(idx, ux, out);
    }
}